// round 10
// baseline (speedup 1.0000x reference)
#include <cuda_runtime.h>
#include <cstdint>

// PureCartesianTensorProductO3Sparse — R10: warp-specialized, rebalanced.
// 4 producer warps (tf32 mma stage-1, 16 n-tiles each) + 16 consumer warps
// (exact fp32 stage-2, 1 output channel per thread). Named barriers count=640.

constexpr int ROW_IN  = 416;
constexpr int TILE    = 32;
constexpr int THREADS = 640;               // 4 producer + 16 consumer warps
constexpr int PTHREADS = 128;              // producer thread count
constexpr int XSTR    = 212;
constexpr int BSTR    = 284;
constexpr int WNF     = 24576;
constexpr int XNF     = TILE * XSTR;       // 6784
constexpr int BNF     = TILE * BSTR;       // 9088
// smem = 24576 + 2*6784 + 2*9088 = 56320 floats = 225280 B

#define BAR_ARRIVE(id) asm volatile("bar.arrive %0, %1;" :: "r"(id), "r"(THREADS) : "memory")
#define BAR_SYNC(id)   asm volatile("bar.sync %0, %1;"   :: "r"(id), "r"(THREADS) : "memory")
// barrier ids: full[slot] = 1 + slot, empty[slot] = 3 + slot

__device__ __forceinline__ uint32_t tf32_of(float f) {
    uint32_t u;
    asm("cvt.rna.tf32.f32 %0, %1;" : "=r"(u) : "f"(f));
    return u;
}

__device__ __forceinline__ void mma_tf32(float& d0, float& d1, float& d2, float& d3,
                                         uint32_t a0, uint32_t a1, uint32_t a2, uint32_t a3,
                                         uint32_t b0, uint32_t b1) {
    asm volatile(
        "mma.sync.aligned.m16n8k8.row.col.f32.tf32.tf32.f32 "
        "{%0,%1,%2,%3}, {%4,%5,%6,%7}, {%8,%9}, {%0,%1,%2,%3};\n"
        : "+f"(d0), "+f"(d1), "+f"(d2), "+f"(d3)
        : "r"(a0), "r"(a1), "r"(a2), "r"(a3), "r"(b0), "r"(b1));
}

__device__ __forceinline__ int bswz(int col) { return col + ((col >> 5) << 2); }

__global__ __launch_bounds__(THREADS, 1)
void tp_o3_mma_kernel(const float* __restrict__ x1,
                      const float* __restrict__ x2,
                      const float* __restrict__ wgt,
                      float* __restrict__ out,
                      int N)
{
    extern __shared__ float smem[];
    float* wsF  = smem;
    float* x1s  = smem + WNF;
    float* x2s  = x1s + XNF;
    float* bufs[2] = { x2s + XNF, x2s + XNF + BNF };

    const int tid = threadIdx.x;

    // ---- weight fill: gmem [p][o][a][b] -> tf32 fragment layout ----
    for (int idx = tid; idx < WNF; idx += THREADS) {
        int p = idx >> 12, o = (idx >> 8) & 15, a = (idx >> 4) & 15, b = idx & 15;
        int slot, col, k;
        if (p < 3)       { slot = p; col = (o << 4) + b; k = a; }
        else if (p == 3) { slot = 3; col = (o << 4) + a; k = b; }
        else if (p == 5) { slot = 4; col = (o << 4) + a; k = b; }
        else             { slot = 5; col = (o << 4) + a; k = b; }
        int fi = ((((slot << 8) + col) << 3) + ((k >> 3) << 2) + (k & 3)) * 2 + ((k >> 2) & 1);
        wsF[fi] = __uint_as_float(tf32_of(wgt[idx]));
    }
    __syncthreads();

    const int lane = tid & 31;
    const int wid  = tid >> 5;
    const bool producer = (wid < 4);

    // consumers pre-arrive both empty slots so producer waits are uniform
    if (!producer) { BAR_ARRIVE(3); BAR_ARRIVE(4); }

    const int ntiles = (N + TILE - 1) / TILE;

    if (producer) {
        // ---------------- PRODUCER: mma stage-1 ----------------
        const int g   = lane >> 2;
        const int tg  = lane & 3;
        const int rb  = wid >> 1;           // rowblock 0/1
        const int nt0 = (wid & 1) << 4;     // 16 n-tiles per warp

        for (int tile = blockIdx.x; tile < ntiles; tile += (int)gridDim.x) {
            const int row0  = tile * TILE;
            const int nrows = min(TILE, N - row0);

            __syncthreads();   // consumers done with previous x
            {
                const float4* g1 = reinterpret_cast<const float4*>(x1) + (size_t)row0 * 104;
                const float4* g2 = reinterpret_cast<const float4*>(x2) + (size_t)row0 * 104;
                float4* s1 = reinterpret_cast<float4*>(x1s);
                float4* s2 = reinterpret_cast<float4*>(x2s);
                for (int i = tid; i < nrows * 52; i += THREADS) {
                    int r = i / 52, c = i - r * 52;
                    s1[r * 53 + c] = g1[(size_t)r * 104 + c];
                    s2[r * 53 + c] = g2[(size_t)r * 104 + c];
                }
            }
            __syncthreads();   // staging complete

            #pragma unroll
            for (int p = 0; p < 8; p++) {
                const int s = p & 1;
                const int  slot = (p < 3) ? p : (p == 3 ? 3 : (p == 4 ? 4 : 5));
                const float* xarr = (p < 3) ? x1s : x2s;
                const int  koff = (p < 5) ? 0 : (16 + (p - 5));
                const int  kmul = (p < 5) ? 1 : 3;

                BAR_SYNC(3 + s);            // wait slot empty
                float* buf = bufs[s];

                uint32_t af[2][4];
                const float* xr0 = xarr + (rb * 16 + g) * XSTR + koff;
                const float* xr1 = xr0 + 8 * XSTR;
                #pragma unroll
                for (int ks = 0; ks < 2; ks++) {
                    int k0 = ks * 8 + tg, k1 = k0 + 4;
                    af[ks][0] = tf32_of(xr0[kmul * k0]);
                    af[ks][1] = tf32_of(xr1[kmul * k0]);
                    af[ks][2] = tf32_of(xr0[kmul * k1]);
                    af[ks][3] = tf32_of(xr1[kmul * k1]);
                }
                #pragma unroll
                for (int j = 0; j < 16; j++) {
                    int nt  = nt0 + j;
                    int col = nt * 8 + g;
                    const float2* bp = reinterpret_cast<const float2*>(wsF)
                                     + (((slot << 8) + col) << 3) + tg;
                    float2 bk0 = bp[0];
                    float2 bk1 = bp[4];
                    uint32_t b00 = __float_as_uint(bk0.x), b01 = __float_as_uint(bk0.y);
                    uint32_t b10 = __float_as_uint(bk1.x), b11 = __float_as_uint(bk1.y);
                    float d0 = 0.f, d1 = 0.f, d2 = 0.f, d3 = 0.f;
                    mma_tf32(d0, d1, d2, d3, af[0][0], af[0][1], af[0][2], af[0][3], b00, b01);
                    mma_tf32(d0, d1, d2, d3, af[1][0], af[1][1], af[1][2], af[1][3], b10, b11);
                    int r0 = rb * 16 + g;
                    int pc = bswz(nt * 8 + 2 * tg);
                    *reinterpret_cast<float2*>(buf + r0 * BSTR + pc)       = make_float2(d0, d1);
                    *reinterpret_cast<float2*>(buf + (r0 + 8) * BSTR + pc) = make_float2(d2, d3);
                }
                BAR_ARRIVE(1 + s);          // slot full
            }

            // zero the s=1 output half while consumers finish
            {
                float4 z = make_float4(0.f, 0.f, 0.f, 0.f);
                float4* og = reinterpret_cast<float4*>(out) + (size_t)row0 * 104;
                for (int i = tid; i < nrows * 52; i += PTHREADS) {
                    int r = i / 52, c = i - r * 52;
                    og[(size_t)r * 104 + 52 + c] = z;
                }
            }
        }
    } else {
        // ---------------- CONSUMER: fp32 stage-2, 1 o-channel/thread --------
        const int ctid = tid - PTHREADS;    // 0..511
        const int row  = ctid >> 4;         // 0..31
        const int o    = ctid & 15;
        const int toff = bswz(o << 4);

        float t[16];

        for (int tile = blockIdx.x; tile < ntiles; tile += (int)gridDim.x) {
            const int row0  = tile * TILE;
            const int nrows = min(TILE, N - row0);
            const bool valid = (row < nrows);

            __syncthreads();
            {
                const float4* g1 = reinterpret_cast<const float4*>(x1) + (size_t)row0 * 104;
                const float4* g2 = reinterpret_cast<const float4*>(x2) + (size_t)row0 * 104;
                float4* s1 = reinterpret_cast<float4*>(x1s);
                float4* s2 = reinterpret_cast<float4*>(x2s);
                for (int i = tid; i < nrows * 52; i += THREADS) {
                    int r = i / 52, c = i - r * 52;
                    s1[r * 53 + c] = g1[(size_t)r * 104 + c];
                    s2[r * 53 + c] = g2[(size_t)r * 104 + c];
                }
            }
            __syncthreads();

            const float* xa = x1s + row * XSTR;
            const float* xb = x2s + row * XSTR;

            float acc0 = 0.f;
            float acc1[3] = {0.f, 0.f, 0.f};
            float acc2[9] = {0.f,0.f,0.f,0.f,0.f,0.f,0.f,0.f,0.f};

            auto load_t = [&](const float* buf) {
                const float4* p = reinterpret_cast<const float4*>(buf + row * BSTR + toff);
                #pragma unroll
                for (int j = 0; j < 4; j++) {
                    float4 q = p[j];
                    t[4*j] = q.x; t[4*j+1] = q.y; t[4*j+2] = q.z; t[4*j+3] = q.w;
                }
            };

            #pragma unroll
            for (int p = 0; p < 8; p++) {
                const int s = p & 1;
                BAR_SYNC(1 + s);            // wait slot full
                if (valid) {
                    load_t(bufs[s]);
                    if (p == 0) {
                        float u0 = 0.f, u1 = 0.f;
                        #pragma unroll
                        for (int b = 0; b < 16; b += 2) {
                            u0 = fmaf(t[b],   xb[b],   u0);
                            u1 = fmaf(t[b+1], xb[b+1], u1);
                        }
                        acc0 = u0 + u1;
                    } else if (p == 1) {
                        #pragma unroll
                        for (int b = 0; b < 16; b++) {
                            float tb = t[b];
                            acc1[0] = fmaf(tb, xb[16 + 3*b + 0], acc1[0]);
                            acc1[1] = fmaf(tb, xb[16 + 3*b + 1], acc1[1]);
                            acc1[2] = fmaf(tb, xb[16 + 3*b + 2], acc1[2]);
                        }
                    } else if (p == 2) {
                        #pragma unroll
                        for (int b = 0; b < 16; b++) {
                            float tb = t[b];
                            #pragma unroll
                            for (int k = 0; k < 9; k++)
                                acc2[k] = fmaf(tb, xb[64 + 9*b + k], acc2[k]);
                        }
                    } else if (p == 3) {
                        #pragma unroll
                        for (int a = 0; a < 16; a++) {
                            float sv = t[a];
                            acc1[0] = fmaf(sv, xa[16 + 3*a + 0], acc1[0]);
                            acc1[1] = fmaf(sv, xa[16 + 3*a + 1], acc1[1]);
                            acc1[2] = fmaf(sv, xa[16 + 3*a + 2], acc1[2]);
                        }
                    } else if (p == 4) {
                        #pragma unroll
                        for (int a = 0; a < 16; a++) {
                            float sv = t[a];
                            #pragma unroll
                            for (int k = 0; k < 9; k++)
                                acc2[k] = fmaf(sv, xa[64 + 9*a + k], acc2[k]);
                        }
                    } else {
                        const int jj = p - 5;
                        #pragma unroll
                        for (int a = 0; a < 16; a++) {
                            float v = t[a];
                            acc2[0 + jj] = fmaf(v, xa[16 + 3*a + 0], acc2[0 + jj]);
                            acc2[3 + jj] = fmaf(v, xa[16 + 3*a + 1], acc2[3 + jj]);
                            acc2[6 + jj] = fmaf(v, xa[16 + 3*a + 2], acc2[6 + jj]);
                        }
                    }
                }
                BAR_ARRIVE(3 + s);          // slot empty
            }

            // ---- write outputs (first half) ----
            if (valid) {
                float* orow = out + (size_t)(row0 + row) * ROW_IN;
                orow[o] = acc0;
                #pragma unroll
                for (int i = 0; i < 3; i++) orow[16 + 3*o + i] = acc1[i];
                #pragma unroll
                for (int k = 0; k < 9; k++) orow[64 + 9*o + k] = acc2[k];
            }
        }
    }
}

extern "C" void kernel_launch(void* const* d_in, const int* in_sizes, int n_in,
                              void* d_out, int out_size)
{
    const float* x1 = (const float*)d_in[0];
    const float* x2 = (const float*)d_in[1];
    const float* w  = (const float*)d_in[2];
    float* out = (float*)d_out;
    const int N = in_sizes[0] / ROW_IN;

    const int smem_bytes = (WNF + 2 * XNF + 2 * BNF) * (int)sizeof(float);  // 225280

    int smcount = 0;
    cudaDeviceGetAttribute(&smcount, cudaDevAttrMultiProcessorCount, 0);
    if (smcount <= 0) smcount = 148;
    cudaFuncSetAttribute(tp_o3_mma_kernel, cudaFuncAttributeMaxDynamicSharedMemorySize,
                         smem_bytes);

    tp_o3_mma_kernel<<<smcount, THREADS, smem_bytes>>>(x1, x2, w, out, N);
}

// round 11
// speedup vs baseline: 1.1140x; 1.1140x over previous
#include <cuda_runtime.h>
#include <cstdint>

// PureCartesianTensorProductO3Sparse — R11: R9 producer/consumer skeleton +
// transposed x staging so ALL stage-2 reads are LDS.128 over the contraction
// index. Row layout (per input, stride 212):
//   [0..16)   L0[c]
//   [16..64)  L1t[i][16]  (i=0..2)
//   [64..208) L2t[k][16]  (k=0..8)

constexpr int ROW_IN  = 416;
constexpr int TILE    = 32;
constexpr int THREADS = 512;               // 8 producer + 8 consumer warps
constexpr int XSTR    = 212;
constexpr int BSTR    = 284;
constexpr int WNF     = 24576;
constexpr int XNF     = TILE * XSTR;       // 6784
constexpr int BNF     = TILE * BSTR;       // 9088
// smem = 24576 + 2*6784 + 2*9088 = 56320 floats = 225280 B

#define BAR_ARRIVE(id) asm volatile("bar.arrive %0, %1;" :: "r"(id), "r"(THREADS) : "memory")
#define BAR_SYNC(id)   asm volatile("bar.sync %0, %1;"   :: "r"(id), "r"(THREADS) : "memory")

__device__ __forceinline__ uint32_t tf32_of(float f) {
    uint32_t u;
    asm("cvt.rna.tf32.f32 %0, %1;" : "=r"(u) : "f"(f));
    return u;
}

__device__ __forceinline__ void mma_tf32(float& d0, float& d1, float& d2, float& d3,
                                         uint32_t a0, uint32_t a1, uint32_t a2, uint32_t a3,
                                         uint32_t b0, uint32_t b1) {
    asm volatile(
        "mma.sync.aligned.m16n8k8.row.col.f32.tf32.tf32.f32 "
        "{%0,%1,%2,%3}, {%4,%5,%6,%7}, {%8,%9}, {%0,%1,%2,%3};\n"
        : "+f"(d0), "+f"(d1), "+f"(d2), "+f"(d3)
        : "r"(a0), "r"(a1), "r"(a2), "r"(a3), "r"(b0), "r"(b1));
}

__device__ __forceinline__ int bswz(int col) { return col + ((col >> 5) << 2); }

__global__ __launch_bounds__(THREADS, 1)
void tp_o3_mma_kernel(const float* __restrict__ x1,
                      const float* __restrict__ x2,
                      const float* __restrict__ wgt,
                      float* __restrict__ out,
                      int N)
{
    extern __shared__ float smem[];
    float* wsF  = smem;
    float* x1s  = smem + WNF;
    float* x2s  = x1s + XNF;
    float* bufs[2] = { x2s + XNF, x2s + XNF + BNF };

    const int tid = threadIdx.x;

    // ---- weight fill: gmem [p][o][a][b] -> tf32 fragment layout ----
    for (int idx = tid; idx < WNF; idx += THREADS) {
        int p = idx >> 12, o = (idx >> 8) & 15, a = (idx >> 4) & 15, b = idx & 15;
        int slot, col, k;
        if (p < 3)       { slot = p; col = (o << 4) + b; k = a; }
        else if (p == 3) { slot = 3; col = (o << 4) + a; k = b; }
        else if (p == 5) { slot = 4; col = (o << 4) + a; k = b; }
        else             { slot = 5; col = (o << 4) + a; k = b; }
        int fi = ((((slot << 8) + col) << 3) + ((k >> 3) << 2) + (k & 3)) * 2 + ((k >> 2) & 1);
        wsF[fi] = __uint_as_float(tf32_of(wgt[idx]));
    }
    __syncthreads();

    const int lane = tid & 31;
    const int wid  = tid >> 5;
    const bool producer = (wid < 8);

    if (!producer) { BAR_ARRIVE(3); BAR_ARRIVE(4); }

    const int ntiles = (N + TILE - 1) / TILE;

    // transposed staging shared by both roles
    auto stage_x = [&](int row0, int nrows) {
        const float4* g1 = reinterpret_cast<const float4*>(x1) + (size_t)row0 * 104;
        const float4* g2 = reinterpret_cast<const float4*>(x2) + (size_t)row0 * 104;
        for (int i = tid; i < nrows * 52; i += THREADS) {
            int r = i / 52, c4 = i - r * 52;
            float4 v1 = g1[(size_t)r * 104 + c4];
            float4 v2 = g2[(size_t)r * 104 + c4];
            float* d1 = x1s + r * XSTR;
            float* d2 = x2s + r * XSTR;
            int c = c4 << 2;
            if (c4 < 4) {
                *reinterpret_cast<float4*>(d1 + c) = v1;
                *reinterpret_cast<float4*>(d2 + c) = v2;
            } else if (c4 < 16) {
                int q = c - 16;
                d1[16 + (q % 3) * 16 + q / 3]             = v1.x;
                d1[16 + ((q+1) % 3) * 16 + (q+1) / 3]     = v1.y;
                d1[16 + ((q+2) % 3) * 16 + (q+2) / 3]     = v1.z;
                d1[16 + ((q+3) % 3) * 16 + (q+3) / 3]     = v1.w;
                d2[16 + (q % 3) * 16 + q / 3]             = v2.x;
                d2[16 + ((q+1) % 3) * 16 + (q+1) / 3]     = v2.y;
                d2[16 + ((q+2) % 3) * 16 + (q+2) / 3]     = v2.z;
                d2[16 + ((q+3) % 3) * 16 + (q+3) / 3]     = v2.w;
            } else {
                int q = c - 64;
                d1[64 + (q % 9) * 16 + q / 9]             = v1.x;
                d1[64 + ((q+1) % 9) * 16 + (q+1) / 9]     = v1.y;
                d1[64 + ((q+2) % 9) * 16 + (q+2) / 9]     = v1.z;
                d1[64 + ((q+3) % 9) * 16 + (q+3) / 9]     = v1.w;
                d2[64 + (q % 9) * 16 + q / 9]             = v2.x;
                d2[64 + ((q+1) % 9) * 16 + (q+1) / 9]     = v2.y;
                d2[64 + ((q+2) % 9) * 16 + (q+2) / 9]     = v2.z;
                d2[64 + ((q+3) % 9) * 16 + (q+3) / 9]     = v2.w;
            }
        }
    };

    if (producer) {
        // ---------------- PRODUCER: tf32 mma stage-1 ----------------
        const int g   = lane >> 2;
        const int tg  = lane & 3;
        const int rb  = wid >> 2;           // rowblock 0/1
        const int nt0 = (wid & 3) << 3;     // 8 n-tiles per warp

        auto load_af = [&](uint32_t (&af)[2][4], const float* base, int koff) {
            const float* xr0 = base + (rb * 16 + g) * XSTR + koff;
            const float* xr1 = xr0 + 8 * XSTR;
            #pragma unroll
            for (int ks = 0; ks < 2; ks++) {
                int k0 = ks * 8 + tg, k1 = k0 + 4;
                af[ks][0] = tf32_of(xr0[k0]);
                af[ks][1] = tf32_of(xr1[k0]);
                af[ks][2] = tf32_of(xr0[k1]);
                af[ks][3] = tf32_of(xr1[k1]);
            }
        };

        auto mma_pass = [&](int slot, const uint32_t (&af)[2][4], float* buf) {
            #pragma unroll
            for (int j = 0; j < 8; j++) {
                int nt  = nt0 + j;
                int col = nt * 8 + g;
                const float2* bp = reinterpret_cast<const float2*>(wsF)
                                 + (((slot << 8) + col) << 3) + tg;
                float2 bk0 = bp[0];
                float2 bk1 = bp[4];
                uint32_t b00 = __float_as_uint(bk0.x), b01 = __float_as_uint(bk0.y);
                uint32_t b10 = __float_as_uint(bk1.x), b11 = __float_as_uint(bk1.y);
                float d0 = 0.f, d1 = 0.f, d2 = 0.f, d3 = 0.f;
                mma_tf32(d0, d1, d2, d3, af[0][0], af[0][1], af[0][2], af[0][3], b00, b01);
                mma_tf32(d0, d1, d2, d3, af[1][0], af[1][1], af[1][2], af[1][3], b10, b11);
                int r0 = rb * 16 + g;
                int pc = bswz(nt * 8 + 2 * tg);
                *reinterpret_cast<float2*>(buf + r0 * BSTR + pc)       = make_float2(d0, d1);
                *reinterpret_cast<float2*>(buf + (r0 + 8) * BSTR + pc) = make_float2(d2, d3);
            }
        };

        for (int tile = blockIdx.x; tile < ntiles; tile += (int)gridDim.x) {
            const int row0  = tile * TILE;
            const int nrows = min(TILE, N - row0);

            __syncthreads();                // consumers done with previous x
            stage_x(row0, nrows);
            __syncthreads();                // staging complete

            uint32_t afA[2][4], afB[2][4], afV[2][4];
            load_af(afA, x1s, 0);           // A0 (passes 0,1,2)
            load_af(afB, x2s, 0);           // B0 (passes 3,4)

            BAR_SYNC(3); mma_pass(0, afA, bufs[0]); BAR_ARRIVE(1);
            BAR_SYNC(4); mma_pass(1, afA, bufs[1]); BAR_ARRIVE(2);
            BAR_SYNC(3); mma_pass(2, afA, bufs[0]); BAR_ARRIVE(1);
            BAR_SYNC(4); mma_pass(3, afB, bufs[1]); BAR_ARRIVE(2);
            BAR_SYNC(3); mma_pass(4, afB, bufs[0]); BAR_ARRIVE(1);

            load_af(afV, x2s, 16);          // B1t[0]
            BAR_SYNC(4); mma_pass(5, afV, bufs[1]); BAR_ARRIVE(2);
            load_af(afV, x2s, 32);          // B1t[1]
            BAR_SYNC(3); mma_pass(5, afV, bufs[0]); BAR_ARRIVE(1);
            load_af(afV, x2s, 48);          // B1t[2]
            BAR_SYNC(4); mma_pass(5, afV, bufs[1]); BAR_ARRIVE(2);

            // zero the s=1 output half while consumers finish
            {
                float4 z = make_float4(0.f, 0.f, 0.f, 0.f);
                float4* og = reinterpret_cast<float4*>(out) + (size_t)row0 * 104;
                for (int i = tid; i < nrows * 52; i += 256) {
                    int r = i / 52, c = i - r * 52;
                    og[(size_t)r * 104 + 52 + c] = z;
                }
            }
        }
    } else {
        // ---------------- CONSUMER: fp32 stage-2 (vectorized reads) --------
        const int ctid = tid - 256;
        const int row  = ctid >> 3;         // 0..31
        const int os   = ctid & 7;
        const int o1 = os, o2 = os + 8;
        const int toff1 = bswz(o1 << 4);
        const int toff2 = bswz(o2 << 4);

        float t1[16], t2[16];

        auto ld16 = [](float (&e)[16], const float* p) {
            const float4* v = reinterpret_cast<const float4*>(p);
            #pragma unroll
            for (int j = 0; j < 4; j++) {
                float4 q = v[j];
                e[4*j] = q.x; e[4*j+1] = q.y; e[4*j+2] = q.z; e[4*j+3] = q.w;
            }
        };

        for (int tile = blockIdx.x; tile < ntiles; tile += (int)gridDim.x) {
            const int row0  = tile * TILE;
            const int nrows = min(TILE, N - row0);
            const bool valid = (row < nrows);

            __syncthreads();
            stage_x(row0, nrows);
            __syncthreads();

            const float* xa = x1s + row * XSTR;
            const float* xb = x2s + row * XSTR;

            float acc0_1 = 0.f, acc0_2 = 0.f;
            float acc1_1[3] = {0.f,0.f,0.f}, acc1_2[3] = {0.f,0.f,0.f};
            float acc2_1[9] = {0.f,0.f,0.f,0.f,0.f,0.f,0.f,0.f,0.f};
            float acc2_2[9] = {0.f,0.f,0.f,0.f,0.f,0.f,0.f,0.f,0.f};

            auto load_tt = [&](const float* buf) {
                const float4* p1 = reinterpret_cast<const float4*>(buf + row * BSTR + toff1);
                const float4* p2 = reinterpret_cast<const float4*>(buf + row * BSTR + toff2);
                #pragma unroll
                for (int j = 0; j < 4; j++) {
                    float4 q = p1[j];
                    t1[4*j] = q.x; t1[4*j+1] = q.y; t1[4*j+2] = q.z; t1[4*j+3] = q.w;
                    q = p2[j];
                    t2[4*j] = q.x; t2[4*j+1] = q.y; t2[4*j+2] = q.z; t2[4*j+3] = q.w;
                }
            };

            float e[16];

            #pragma unroll
            for (int p = 0; p < 8; p++) {
                const int s = p & 1;
                BAR_SYNC(1 + s);            // wait slot full
                if (valid) {
                    load_tt(bufs[s]);
                    if (p == 0) {
                        ld16(e, xb);
                        float u1a=0.f,u1b=0.f,u2a=0.f,u2b=0.f;
                        #pragma unroll
                        for (int b = 0; b < 16; b += 2) {
                            u1a = fmaf(t1[b],   e[b],   u1a);
                            u1b = fmaf(t1[b+1], e[b+1], u1b);
                            u2a = fmaf(t2[b],   e[b],   u2a);
                            u2b = fmaf(t2[b+1], e[b+1], u2b);
                        }
                        acc0_1 = u1a + u1b; acc0_2 = u2a + u2b;
                    } else if (p == 1) {
                        #pragma unroll
                        for (int i = 0; i < 3; i++) {
                            ld16(e, xb + 16 + 16*i);
                            #pragma unroll
                            for (int b = 0; b < 16; b++) {
                                acc1_1[i] = fmaf(t1[b], e[b], acc1_1[i]);
                                acc1_2[i] = fmaf(t2[b], e[b], acc1_2[i]);
                            }
                        }
                    } else if (p == 2) {
                        #pragma unroll
                        for (int k = 0; k < 9; k++) {
                            ld16(e, xb + 64 + 16*k);
                            #pragma unroll
                            for (int b = 0; b < 16; b++) {
                                acc2_1[k] = fmaf(t1[b], e[b], acc2_1[k]);
                                acc2_2[k] = fmaf(t2[b], e[b], acc2_2[k]);
                            }
                        }
                    } else if (p == 3) {
                        #pragma unroll
                        for (int i = 0; i < 3; i++) {
                            ld16(e, xa + 16 + 16*i);
                            #pragma unroll
                            for (int a = 0; a < 16; a++) {
                                acc1_1[i] = fmaf(t1[a], e[a], acc1_1[i]);
                                acc1_2[i] = fmaf(t2[a], e[a], acc1_2[i]);
                            }
                        }
                    } else if (p == 4) {
                        #pragma unroll
                        for (int k = 0; k < 9; k++) {
                            ld16(e, xa + 64 + 16*k);
                            #pragma unroll
                            for (int a = 0; a < 16; a++) {
                                acc2_1[k] = fmaf(t1[a], e[a], acc2_1[k]);
                                acc2_2[k] = fmaf(t2[a], e[a], acc2_2[k]);
                            }
                        }
                    } else {
                        const int jj = p - 5;
                        #pragma unroll
                        for (int i = 0; i < 3; i++) {
                            ld16(e, xa + 16 + 16*i);
                            #pragma unroll
                            for (int a = 0; a < 16; a++) {
                                acc2_1[3*i + jj] = fmaf(t1[a], e[a], acc2_1[3*i + jj]);
                                acc2_2[3*i + jj] = fmaf(t2[a], e[a], acc2_2[3*i + jj]);
                            }
                        }
                    }
                }
                BAR_ARRIVE(3 + s);          // slot empty
            }

            // ---- write outputs (first half) for both o's ----
            if (valid) {
                float* orow = out + (size_t)(row0 + row) * ROW_IN;
                orow[o1] = acc0_1;
                orow[o2] = acc0_2;
                #pragma unroll
                for (int i = 0; i < 3; i++) {
                    orow[16 + 3*o1 + i] = acc1_1[i];
                    orow[16 + 3*o2 + i] = acc1_2[i];
                }
                #pragma unroll
                for (int k = 0; k < 9; k++) {
                    orow[64 + 9*o1 + k] = acc2_1[k];
                    orow[64 + 9*o2 + k] = acc2_2[k];
                }
            }
        }
    }
}

extern "C" void kernel_launch(void* const* d_in, const int* in_sizes, int n_in,
                              void* d_out, int out_size)
{
    const float* x1 = (const float*)d_in[0];
    const float* x2 = (const float*)d_in[1];
    const float* w  = (const float*)d_in[2];
    float* out = (float*)d_out;
    const int N = in_sizes[0] / ROW_IN;

    const int smem_bytes = (WNF + 2 * XNF + 2 * BNF) * (int)sizeof(float);  // 225280

    int smcount = 0;
    cudaDeviceGetAttribute(&smcount, cudaDevAttrMultiProcessorCount, 0);
    if (smcount <= 0) smcount = 148;
    cudaFuncSetAttribute(tp_o3_mma_kernel, cudaFuncAttributeMaxDynamicSharedMemorySize,
                         smem_bytes);

    tp_o3_mma_kernel<<<smcount, THREADS, smem_bytes>>>(x1, x2, w, out, N);
}

// round 12
// speedup vs baseline: 1.1153x; 1.0012x over previous
#include <cuda_runtime.h>
#include <cstdint>

// PureCartesianTensorProductO3Sparse — R12: R9 skeleton, rebalanced 8P+16C.
// Producers (warps 0-7): tf32 mma stage-1, 8 n-tiles each — identical to R9.
// Consumers (warps 8-23): fp32 stage-2, ONE output channel per thread
// (512 threads = 32 rows x 16 o). Named barriers count = 768.

constexpr int ROW_IN  = 416;
constexpr int TILE    = 32;
constexpr int THREADS = 768;               // 8 producer + 16 consumer warps
constexpr int PTHREADS = 256;
constexpr int XSTR    = 212;
constexpr int BSTR    = 284;
constexpr int WNF     = 24576;
constexpr int XNF     = TILE * XSTR;       // 6784
constexpr int BNF     = TILE * BSTR;       // 9088
// smem = 24576 + 2*6784 + 2*9088 = 56320 floats = 225280 B

#define BAR_ARRIVE(id) asm volatile("bar.arrive %0, %1;" :: "r"(id), "r"(THREADS) : "memory")
#define BAR_SYNC(id)   asm volatile("bar.sync %0, %1;"   :: "r"(id), "r"(THREADS) : "memory")
// barrier ids: full[slot] = 1 + slot, empty[slot] = 3 + slot

__device__ __forceinline__ uint32_t tf32_of(float f) {
    uint32_t u;
    asm("cvt.rna.tf32.f32 %0, %1;" : "=r"(u) : "f"(f));
    return u;
}

__device__ __forceinline__ void mma_tf32(float& d0, float& d1, float& d2, float& d3,
                                         uint32_t a0, uint32_t a1, uint32_t a2, uint32_t a3,
                                         uint32_t b0, uint32_t b1) {
    asm volatile(
        "mma.sync.aligned.m16n8k8.row.col.f32.tf32.tf32.f32 "
        "{%0,%1,%2,%3}, {%4,%5,%6,%7}, {%8,%9}, {%0,%1,%2,%3};\n"
        : "+f"(d0), "+f"(d1), "+f"(d2), "+f"(d3)
        : "r"(a0), "r"(a1), "r"(a2), "r"(a3), "r"(b0), "r"(b1));
}

__device__ __forceinline__ int bswz(int col) { return col + ((col >> 5) << 2); }

__global__ __launch_bounds__(THREADS, 1)
void tp_o3_mma_kernel(const float* __restrict__ x1,
                      const float* __restrict__ x2,
                      const float* __restrict__ wgt,
                      float* __restrict__ out,
                      int N)
{
    extern __shared__ float smem[];
    float* wsF  = smem;
    float* x1s  = smem + WNF;
    float* x2s  = x1s + XNF;
    float* bufs[2] = { x2s + XNF, x2s + XNF + BNF };

    const int tid = threadIdx.x;

    // ---- weight fill: gmem [p][o][a][b] -> tf32 fragment layout ----
    for (int idx = tid; idx < WNF; idx += THREADS) {
        int p = idx >> 12, o = (idx >> 8) & 15, a = (idx >> 4) & 15, b = idx & 15;
        int slot, col, k;
        if (p < 3)       { slot = p; col = (o << 4) + b; k = a; }
        else if (p == 3) { slot = 3; col = (o << 4) + a; k = b; }
        else if (p == 5) { slot = 4; col = (o << 4) + a; k = b; }
        else             { slot = 5; col = (o << 4) + a; k = b; }
        int fi = ((((slot << 8) + col) << 3) + ((k >> 3) << 2) + (k & 3)) * 2 + ((k >> 2) & 1);
        wsF[fi] = __uint_as_float(tf32_of(wgt[idx]));
    }
    __syncthreads();

    const int lane = tid & 31;
    const int wid  = tid >> 5;
    const bool producer = (wid < 8);

    // consumers pre-arrive both empty slots so producer waits are uniform
    if (!producer) { BAR_ARRIVE(3); BAR_ARRIVE(4); }

    const int ntiles = (N + TILE - 1) / TILE;

    if (producer) {
        // ---------------- PRODUCER: mma stage-1 (identical to R9) -----------
        const int g   = lane >> 2;
        const int tg  = lane & 3;
        const int rb  = wid >> 2;           // rowblock 0/1
        const int nt0 = (wid & 3) << 3;     // 8 n-tiles per warp

        for (int tile = blockIdx.x; tile < ntiles; tile += (int)gridDim.x) {
            const int row0  = tile * TILE;
            const int nrows = min(TILE, N - row0);

            __syncthreads();   // consumers done with previous x
            {
                const float4* g1 = reinterpret_cast<const float4*>(x1) + (size_t)row0 * 104;
                const float4* g2 = reinterpret_cast<const float4*>(x2) + (size_t)row0 * 104;
                float4* s1 = reinterpret_cast<float4*>(x1s);
                float4* s2 = reinterpret_cast<float4*>(x2s);
                for (int i = tid; i < nrows * 52; i += THREADS) {
                    int r = i / 52, c = i - r * 52;
                    s1[r * 53 + c] = g1[(size_t)r * 104 + c];
                    s2[r * 53 + c] = g2[(size_t)r * 104 + c];
                }
            }
            __syncthreads();   // staging complete

            #pragma unroll
            for (int p = 0; p < 8; p++) {
                const int s = p & 1;
                const int  slot = (p < 3) ? p : (p == 3 ? 3 : (p == 4 ? 4 : 5));
                const float* xarr = (p < 3) ? x1s : x2s;
                const int  koff = (p < 5) ? 0 : (16 + (p - 5));
                const int  kmul = (p < 5) ? 1 : 3;

                BAR_SYNC(3 + s);            // wait slot empty
                float* buf = bufs[s];

                uint32_t af[2][4];
                const float* xr0 = xarr + (rb * 16 + g) * XSTR + koff;
                const float* xr1 = xr0 + 8 * XSTR;
                #pragma unroll
                for (int ks = 0; ks < 2; ks++) {
                    int k0 = ks * 8 + tg, k1 = k0 + 4;
                    af[ks][0] = tf32_of(xr0[kmul * k0]);
                    af[ks][1] = tf32_of(xr1[kmul * k0]);
                    af[ks][2] = tf32_of(xr0[kmul * k1]);
                    af[ks][3] = tf32_of(xr1[kmul * k1]);
                }
                #pragma unroll
                for (int j = 0; j < 8; j++) {
                    int nt  = nt0 + j;
                    int col = nt * 8 + g;
                    const float2* bp = reinterpret_cast<const float2*>(wsF)
                                     + (((slot << 8) + col) << 3) + tg;
                    float2 bk0 = bp[0];
                    float2 bk1 = bp[4];
                    uint32_t b00 = __float_as_uint(bk0.x), b01 = __float_as_uint(bk0.y);
                    uint32_t b10 = __float_as_uint(bk1.x), b11 = __float_as_uint(bk1.y);
                    float d0 = 0.f, d1 = 0.f, d2 = 0.f, d3 = 0.f;
                    mma_tf32(d0, d1, d2, d3, af[0][0], af[0][1], af[0][2], af[0][3], b00, b01);
                    mma_tf32(d0, d1, d2, d3, af[1][0], af[1][1], af[1][2], af[1][3], b10, b11);
                    int r0 = rb * 16 + g;
                    int pc = bswz(nt * 8 + 2 * tg);
                    *reinterpret_cast<float2*>(buf + r0 * BSTR + pc)       = make_float2(d0, d1);
                    *reinterpret_cast<float2*>(buf + (r0 + 8) * BSTR + pc) = make_float2(d2, d3);
                }
                BAR_ARRIVE(1 + s);          // slot full
            }

            // zero the s=1 output half while consumers finish
            {
                float4 z = make_float4(0.f, 0.f, 0.f, 0.f);
                float4* og = reinterpret_cast<float4*>(out) + (size_t)row0 * 104;
                for (int i = tid; i < nrows * 52; i += PTHREADS) {
                    int r = i / 52, c = i - r * 52;
                    og[(size_t)r * 104 + 52 + c] = z;
                }
            }
        }
    } else {
        // ---------------- CONSUMER: fp32 stage-2, 1 o-channel/thread --------
        const int ctid = tid - PTHREADS;    // 0..511
        const int row  = ctid >> 4;         // 0..31
        const int o    = ctid & 15;
        const int toff = bswz(o << 4);

        float t[16];

        for (int tile = blockIdx.x; tile < ntiles; tile += (int)gridDim.x) {
            const int row0  = tile * TILE;
            const int nrows = min(TILE, N - row0);
            const bool valid = (row < nrows);

            __syncthreads();
            {
                const float4* g1 = reinterpret_cast<const float4*>(x1) + (size_t)row0 * 104;
                const float4* g2 = reinterpret_cast<const float4*>(x2) + (size_t)row0 * 104;
                float4* s1 = reinterpret_cast<float4*>(x1s);
                float4* s2 = reinterpret_cast<float4*>(x2s);
                for (int i = tid; i < nrows * 52; i += THREADS) {
                    int r = i / 52, c = i - r * 52;
                    s1[r * 53 + c] = g1[(size_t)r * 104 + c];
                    s2[r * 53 + c] = g2[(size_t)r * 104 + c];
                }
            }
            __syncthreads();

            const float* xa = x1s + row * XSTR;
            const float* xb = x2s + row * XSTR;

            float acc0 = 0.f;
            float acc1[3] = {0.f, 0.f, 0.f};
            float acc2[9] = {0.f,0.f,0.f,0.f,0.f,0.f,0.f,0.f,0.f};

            auto load_t = [&](const float* buf) {
                const float4* p = reinterpret_cast<const float4*>(buf + row * BSTR + toff);
                #pragma unroll
                for (int j = 0; j < 4; j++) {
                    float4 q = p[j];
                    t[4*j] = q.x; t[4*j+1] = q.y; t[4*j+2] = q.z; t[4*j+3] = q.w;
                }
            };

            #pragma unroll
            for (int p = 0; p < 8; p++) {
                const int s = p & 1;
                BAR_SYNC(1 + s);            // wait slot full
                if (valid) {
                    load_t(bufs[s]);
                    if (p == 0) {
                        float u0 = 0.f, u1 = 0.f;
                        #pragma unroll
                        for (int b = 0; b < 16; b += 2) {
                            u0 = fmaf(t[b],   xb[b],   u0);
                            u1 = fmaf(t[b+1], xb[b+1], u1);
                        }
                        acc0 = u0 + u1;
                    } else if (p == 1) {
                        #pragma unroll
                        for (int b = 0; b < 16; b++) {
                            float tb = t[b];
                            acc1[0] = fmaf(tb, xb[16 + 3*b + 0], acc1[0]);
                            acc1[1] = fmaf(tb, xb[16 + 3*b + 1], acc1[1]);
                            acc1[2] = fmaf(tb, xb[16 + 3*b + 2], acc1[2]);
                        }
                    } else if (p == 2) {
                        #pragma unroll
                        for (int b = 0; b < 16; b++) {
                            float tb = t[b];
                            #pragma unroll
                            for (int k = 0; k < 9; k++)
                                acc2[k] = fmaf(tb, xb[64 + 9*b + k], acc2[k]);
                        }
                    } else if (p == 3) {
                        #pragma unroll
                        for (int a = 0; a < 16; a++) {
                            float sv = t[a];
                            acc1[0] = fmaf(sv, xa[16 + 3*a + 0], acc1[0]);
                            acc1[1] = fmaf(sv, xa[16 + 3*a + 1], acc1[1]);
                            acc1[2] = fmaf(sv, xa[16 + 3*a + 2], acc1[2]);
                        }
                    } else if (p == 4) {
                        #pragma unroll
                        for (int a = 0; a < 16; a++) {
                            float sv = t[a];
                            #pragma unroll
                            for (int k = 0; k < 9; k++)
                                acc2[k] = fmaf(sv, xa[64 + 9*a + k], acc2[k]);
                        }
                    } else {
                        const int jj = p - 5;
                        #pragma unroll
                        for (int a = 0; a < 16; a++) {
                            float v = t[a];
                            acc2[0 + jj] = fmaf(v, xa[16 + 3*a + 0], acc2[0 + jj]);
                            acc2[3 + jj] = fmaf(v, xa[16 + 3*a + 1], acc2[3 + jj]);
                            acc2[6 + jj] = fmaf(v, xa[16 + 3*a + 2], acc2[6 + jj]);
                        }
                    }
                }
                BAR_ARRIVE(3 + s);          // slot empty
            }

            // ---- write outputs (first half) ----
            if (valid) {
                float* orow = out + (size_t)(row0 + row) * ROW_IN;
                orow[o] = acc0;
                #pragma unroll
                for (int i = 0; i < 3; i++) orow[16 + 3*o + i] = acc1[i];
                #pragma unroll
                for (int k = 0; k < 9; k++) orow[64 + 9*o + k] = acc2[k];
            }
        }
    }
}

extern "C" void kernel_launch(void* const* d_in, const int* in_sizes, int n_in,
                              void* d_out, int out_size)
{
    const float* x1 = (const float*)d_in[0];
    const float* x2 = (const float*)d_in[1];
    const float* w  = (const float*)d_in[2];
    float* out = (float*)d_out;
    const int N = in_sizes[0] / ROW_IN;

    const int smem_bytes = (WNF + 2 * XNF + 2 * BNF) * (int)sizeof(float);  // 225280

    int smcount = 0;
    cudaDeviceGetAttribute(&smcount, cudaDevAttrMultiProcessorCount, 0);
    if (smcount <= 0) smcount = 148;
    cudaFuncSetAttribute(tp_o3_mma_kernel, cudaFuncAttributeMaxDynamicSharedMemorySize,
                         smem_bytes);

    tp_o3_mma_kernel<<<smcount, THREADS, smem_bytes>>>(x1, x2, w, out, N);
}

// round 13
// speedup vs baseline: 1.3025x; 1.1678x over previous
#include <cuda_runtime.h>
#include <cuda_fp16.h>
#include <cstdint>

// PureCartesianTensorProductO3Sparse — R13: R9 skeleton + 3-slot pipeline.
// Weights stored as fp16 fragments (same 10-bit mantissa as tf32 -> identical
// rounding error); the 48 KB saved funds a third stage-1 buffer slot, which
// decouples producer/consumer jitter (2-deep was lock-step).

constexpr int ROW_IN  = 416;
constexpr int TILE    = 32;
constexpr int THREADS = 512;               // 8 producer + 8 consumer warps
constexpr int PTHREADS = 256;
constexpr int XSTR    = 212;
constexpr int BSTR    = 284;
constexpr int WELEMS  = 24576;
constexpr int WHF     = WELEMS / 2;        // half-weights, in float-equivalents
constexpr int XNF     = TILE * XSTR;       // 6784
constexpr int BNF     = TILE * BSTR;       // 9088
// smem = 12288 + 2*6784 + 3*9088 = 53120 floats = 212480 B

#define BAR_ARRIVE(id) asm volatile("bar.arrive %0, %1;" :: "r"(id), "r"(THREADS) : "memory")
#define BAR_SYNC(id)   asm volatile("bar.sync %0, %1;"   :: "r"(id), "r"(THREADS) : "memory")
// barrier ids: full[slot] = 1 + slot, empty[slot] = 4 + slot  (slots 0..2)

__device__ __forceinline__ uint32_t tf32_of(float f) {
    uint32_t u;
    asm("cvt.rna.tf32.f32 %0, %1;" : "=r"(u) : "f"(f));
    return u;
}

__device__ __forceinline__ void mma_tf32(float& d0, float& d1, float& d2, float& d3,
                                         uint32_t a0, uint32_t a1, uint32_t a2, uint32_t a3,
                                         uint32_t b0, uint32_t b1) {
    asm volatile(
        "mma.sync.aligned.m16n8k8.row.col.f32.tf32.tf32.f32 "
        "{%0,%1,%2,%3}, {%4,%5,%6,%7}, {%8,%9}, {%0,%1,%2,%3};\n"
        : "+f"(d0), "+f"(d1), "+f"(d2), "+f"(d3)
        : "r"(a0), "r"(a1), "r"(a2), "r"(a3), "r"(b0), "r"(b1));
}

__device__ __forceinline__ int bswz(int col) { return col + ((col >> 5) << 2); }

__global__ __launch_bounds__(THREADS, 1)
void tp_o3_mma_kernel(const float* __restrict__ x1,
                      const float* __restrict__ x2,
                      const float* __restrict__ wgt,
                      float* __restrict__ out,
                      int N)
{
    extern __shared__ float smem[];
    __half* wsH = reinterpret_cast<__half*>(smem);   // fp16 weight fragments
    float* x1s  = smem + WHF;
    float* x2s  = x1s + XNF;
    float* bufs[3] = { x2s + XNF, x2s + XNF + BNF, x2s + XNF + 2 * BNF };

    const int tid = threadIdx.x;

    // ---- weight fill: gmem [p][o][a][b] -> fp16 fragment layout ----
    // per col: 16 halves, pos(k) = ((k&3)<<2) | ((k>>3)<<1) | ((k>>2)&1)
    for (int idx = tid; idx < WELEMS; idx += THREADS) {
        int p = idx >> 12, o = (idx >> 8) & 15, a = (idx >> 4) & 15, b = idx & 15;
        int slot, col, k;
        if (p < 3)       { slot = p; col = (o << 4) + b; k = a; }
        else if (p == 3) { slot = 3; col = (o << 4) + a; k = b; }
        else if (p == 5) { slot = 4; col = (o << 4) + a; k = b; }
        else             { slot = 5; col = (o << 4) + a; k = b; }
        int pos = ((k & 3) << 2) | ((k >> 3) << 1) | ((k >> 2) & 1);
        wsH[(((slot << 8) + col) << 4) + pos] = __float2half(wgt[idx]);
    }
    __syncthreads();

    const int lane = tid & 31;
    const int wid  = tid >> 5;
    const bool producer = (wid < 8);

    // consumers pre-arrive all three empty slots
    if (!producer) { BAR_ARRIVE(4); BAR_ARRIVE(5); BAR_ARRIVE(6); }

    const int ntiles = (N + TILE - 1) / TILE;

    if (producer) {
        // ---------------- PRODUCER: tf32 mma stage-1 ----------------
        const int g   = lane >> 2;
        const int tg  = lane & 3;
        const int rb  = wid >> 2;           // rowblock 0/1
        const int nt0 = (wid & 3) << 3;     // 8 n-tiles per warp

        auto load_af = [&](uint32_t (&af)[2][4], const float* base, int koff, int kmul) {
            const float* xr0 = base + (rb * 16 + g) * XSTR + koff;
            const float* xr1 = xr0 + 8 * XSTR;
            #pragma unroll
            for (int ks = 0; ks < 2; ks++) {
                int k0 = ks * 8 + tg, k1 = k0 + 4;
                af[ks][0] = tf32_of(xr0[kmul * k0]);
                af[ks][1] = tf32_of(xr1[kmul * k0]);
                af[ks][2] = tf32_of(xr0[kmul * k1]);
                af[ks][3] = tf32_of(xr1[kmul * k1]);
            }
        };

        auto mma_pass = [&](int slot, const uint32_t (&af)[2][4], float* buf) {
            #pragma unroll
            for (int j = 0; j < 8; j++) {
                int nt  = nt0 + j;
                int col = nt * 8 + g;
                const uint2* bp = reinterpret_cast<const uint2*>(wsH)
                                + (((slot << 8) + col) << 2) + tg;
                uint2 hw = *bp;
                __half2 h0 = *reinterpret_cast<__half2*>(&hw.x);  // (k=tg, k=tg+4)
                __half2 h1 = *reinterpret_cast<__half2*>(&hw.y);  // (k=8+tg, 12+tg)
                float2 f0 = __half22float2(h0);
                float2 f1 = __half22float2(h1);
                uint32_t b00 = __float_as_uint(f0.x), b01 = __float_as_uint(f0.y);
                uint32_t b10 = __float_as_uint(f1.x), b11 = __float_as_uint(f1.y);
                float d0 = 0.f, d1 = 0.f, d2 = 0.f, d3 = 0.f;
                mma_tf32(d0, d1, d2, d3, af[0][0], af[0][1], af[0][2], af[0][3], b00, b01);
                mma_tf32(d0, d1, d2, d3, af[1][0], af[1][1], af[1][2], af[1][3], b10, b11);
                int r0 = rb * 16 + g;
                int pc = bswz(nt * 8 + 2 * tg);
                *reinterpret_cast<float2*>(buf + r0 * BSTR + pc)       = make_float2(d0, d1);
                *reinterpret_cast<float2*>(buf + (r0 + 8) * BSTR + pc) = make_float2(d2, d3);
            }
        };

        for (int tile = blockIdx.x; tile < ntiles; tile += (int)gridDim.x) {
            const int row0  = tile * TILE;
            const int nrows = min(TILE, N - row0);

            __syncthreads();   // consumers done with previous x
            {
                const float4* g1 = reinterpret_cast<const float4*>(x1) + (size_t)row0 * 104;
                const float4* g2 = reinterpret_cast<const float4*>(x2) + (size_t)row0 * 104;
                float4* s1 = reinterpret_cast<float4*>(x1s);
                float4* s2 = reinterpret_cast<float4*>(x2s);
                for (int i = tid; i < nrows * 52; i += THREADS) {
                    int r = i / 52, c = i - r * 52;
                    s1[r * 53 + c] = g1[(size_t)r * 104 + c];
                    s2[r * 53 + c] = g2[(size_t)r * 104 + c];
                }
            }
            __syncthreads();   // staging complete

            uint32_t afA[2][4], afB[2][4], afV[2][4];
            load_af(afA, x1s, 0, 1);        // A0 (passes 0,1,2)
            load_af(afB, x2s, 0, 1);        // B0 (passes 3,4)

            BAR_SYNC(4); mma_pass(0, afA, bufs[0]); BAR_ARRIVE(1);
            BAR_SYNC(5); mma_pass(1, afA, bufs[1]); BAR_ARRIVE(2);
            BAR_SYNC(6); mma_pass(2, afA, bufs[2]); BAR_ARRIVE(3);
            BAR_SYNC(4); mma_pass(3, afB, bufs[0]); BAR_ARRIVE(1);
            BAR_SYNC(5); mma_pass(4, afB, bufs[1]); BAR_ARRIVE(2);

            load_af(afV, x2s, 16, 3);       // B1t[0]
            BAR_SYNC(6); mma_pass(5, afV, bufs[2]); BAR_ARRIVE(3);
            load_af(afV, x2s, 17, 3);       // B1t[1]
            BAR_SYNC(4); mma_pass(5, afV, bufs[0]); BAR_ARRIVE(1);
            load_af(afV, x2s, 18, 3);       // B1t[2]
            BAR_SYNC(5); mma_pass(5, afV, bufs[1]); BAR_ARRIVE(2);

            // zero the s=1 output half while consumers finish
            {
                float4 z = make_float4(0.f, 0.f, 0.f, 0.f);
                float4* og = reinterpret_cast<float4*>(out) + (size_t)row0 * 104;
                for (int i = tid; i < nrows * 52; i += PTHREADS) {
                    int r = i / 52, c = i - r * 52;
                    og[(size_t)r * 104 + 52 + c] = z;
                }
            }
        }
    } else {
        // ---------------- CONSUMER: fp32 stage-2, 2 o-channels/thread -------
        const int ctid = tid - PTHREADS;
        const int row  = ctid >> 3;         // 0..31
        const int os   = ctid & 7;
        const int o1 = os, o2 = os + 8;
        const int toff1 = bswz(o1 << 4);
        const int toff2 = bswz(o2 << 4);

        float t1[16], t2[16];

        for (int tile = blockIdx.x; tile < ntiles; tile += (int)gridDim.x) {
            const int row0  = tile * TILE;
            const int nrows = min(TILE, N - row0);
            const bool valid = (row < nrows);

            __syncthreads();
            {
                const float4* g1 = reinterpret_cast<const float4*>(x1) + (size_t)row0 * 104;
                const float4* g2 = reinterpret_cast<const float4*>(x2) + (size_t)row0 * 104;
                float4* s1 = reinterpret_cast<float4*>(x1s);
                float4* s2 = reinterpret_cast<float4*>(x2s);
                for (int i = tid; i < nrows * 52; i += THREADS) {
                    int r = i / 52, c = i - r * 52;
                    s1[r * 53 + c] = g1[(size_t)r * 104 + c];
                    s2[r * 53 + c] = g2[(size_t)r * 104 + c];
                }
            }
            __syncthreads();

            const float* xa = x1s + row * XSTR;
            const float* xb = x2s + row * XSTR;

            float acc0_1 = 0.f, acc0_2 = 0.f;
            float acc1_1[3] = {0.f,0.f,0.f}, acc1_2[3] = {0.f,0.f,0.f};
            float acc2_1[9] = {0.f,0.f,0.f,0.f,0.f,0.f,0.f,0.f,0.f};
            float acc2_2[9] = {0.f,0.f,0.f,0.f,0.f,0.f,0.f,0.f,0.f};

            auto load_tt = [&](const float* buf) {
                const float4* p1 = reinterpret_cast<const float4*>(buf + row * BSTR + toff1);
                const float4* p2 = reinterpret_cast<const float4*>(buf + row * BSTR + toff2);
                #pragma unroll
                for (int j = 0; j < 4; j++) {
                    float4 q = p1[j];
                    t1[4*j] = q.x; t1[4*j+1] = q.y; t1[4*j+2] = q.z; t1[4*j+3] = q.w;
                    q = p2[j];
                    t2[4*j] = q.x; t2[4*j+1] = q.y; t2[4*j+2] = q.z; t2[4*j+3] = q.w;
                }
            };

            #pragma unroll
            for (int p = 0; p < 8; p++) {
                const int s = p % 3;
                BAR_SYNC(1 + s);            // wait slot full
                if (valid) {
                    load_tt(bufs[s]);
                    if (p == 0) {
                        float u1a=0.f,u1b=0.f,u2a=0.f,u2b=0.f;
                        #pragma unroll
                        for (int b = 0; b < 16; b += 2) {
                            float e0 = xb[b], e1 = xb[b+1];
                            u1a = fmaf(t1[b],   e0, u1a);
                            u1b = fmaf(t1[b+1], e1, u1b);
                            u2a = fmaf(t2[b],   e0, u2a);
                            u2b = fmaf(t2[b+1], e1, u2b);
                        }
                        acc0_1 = u1a + u1b; acc0_2 = u2a + u2b;
                    } else if (p == 1) {
                        #pragma unroll
                        for (int b = 0; b < 16; b++) {
                            float e0 = xb[16 + 3*b + 0];
                            float e1 = xb[16 + 3*b + 1];
                            float e2 = xb[16 + 3*b + 2];
                            acc1_1[0] = fmaf(t1[b], e0, acc1_1[0]);
                            acc1_1[1] = fmaf(t1[b], e1, acc1_1[1]);
                            acc1_1[2] = fmaf(t1[b], e2, acc1_1[2]);
                            acc1_2[0] = fmaf(t2[b], e0, acc1_2[0]);
                            acc1_2[1] = fmaf(t2[b], e1, acc1_2[1]);
                            acc1_2[2] = fmaf(t2[b], e2, acc1_2[2]);
                        }
                    } else if (p == 2) {
                        #pragma unroll
                        for (int b = 0; b < 16; b++) {
                            float tb1 = t1[b], tb2 = t2[b];
                            #pragma unroll
                            for (int k = 0; k < 9; k++) {
                                float e = xb[64 + 9*b + k];
                                acc2_1[k] = fmaf(tb1, e, acc2_1[k]);
                                acc2_2[k] = fmaf(tb2, e, acc2_2[k]);
                            }
                        }
                    } else if (p == 3) {
                        #pragma unroll
                        for (int a = 0; a < 16; a++) {
                            float e0 = xa[16 + 3*a + 0];
                            float e1 = xa[16 + 3*a + 1];
                            float e2 = xa[16 + 3*a + 2];
                            acc1_1[0] = fmaf(t1[a], e0, acc1_1[0]);
                            acc1_1[1] = fmaf(t1[a], e1, acc1_1[1]);
                            acc1_1[2] = fmaf(t1[a], e2, acc1_1[2]);
                            acc1_2[0] = fmaf(t2[a], e0, acc1_2[0]);
                            acc1_2[1] = fmaf(t2[a], e1, acc1_2[1]);
                            acc1_2[2] = fmaf(t2[a], e2, acc1_2[2]);
                        }
                    } else if (p == 4) {
                        #pragma unroll
                        for (int a = 0; a < 16; a++) {
                            float s1v = t1[a], s2v = t2[a];
                            #pragma unroll
                            for (int k = 0; k < 9; k++) {
                                float e = xa[64 + 9*a + k];
                                acc2_1[k] = fmaf(s1v, e, acc2_1[k]);
                                acc2_2[k] = fmaf(s2v, e, acc2_2[k]);
                            }
                        }
                    } else {
                        const int jj = p - 5;
                        #pragma unroll
                        for (int a = 0; a < 16; a++) {
                            float v1 = t1[a], v2 = t2[a];
                            float e0 = xa[16 + 3*a + 0];
                            float e1 = xa[16 + 3*a + 1];
                            float e2 = xa[16 + 3*a + 2];
                            acc2_1[0 + jj] = fmaf(v1, e0, acc2_1[0 + jj]);
                            acc2_1[3 + jj] = fmaf(v1, e1, acc2_1[3 + jj]);
                            acc2_1[6 + jj] = fmaf(v1, e2, acc2_1[6 + jj]);
                            acc2_2[0 + jj] = fmaf(v2, e0, acc2_2[0 + jj]);
                            acc2_2[3 + jj] = fmaf(v2, e1, acc2_2[3 + jj]);
                            acc2_2[6 + jj] = fmaf(v2, e2, acc2_2[6 + jj]);
                        }
                    }
                }
                BAR_ARRIVE(4 + s);          // slot empty
            }

            // ---- write outputs (first half) for both o's ----
            if (valid) {
                float* orow = out + (size_t)(row0 + row) * ROW_IN;
                orow[o1] = acc0_1;
                orow[o2] = acc0_2;
                #pragma unroll
                for (int i = 0; i < 3; i++) {
                    orow[16 + 3*o1 + i] = acc1_1[i];
                    orow[16 + 3*o2 + i] = acc1_2[i];
                }
                #pragma unroll
                for (int k = 0; k < 9; k++) {
                    orow[64 + 9*o1 + k] = acc2_1[k];
                    orow[64 + 9*o2 + k] = acc2_2[k];
                }
            }
        }
    }
}

extern "C" void kernel_launch(void* const* d_in, const int* in_sizes, int n_in,
                              void* d_out, int out_size)
{
    const float* x1 = (const float*)d_in[0];
    const float* x2 = (const float*)d_in[1];
    const float* w  = (const float*)d_in[2];
    float* out = (float*)d_out;
    const int N = in_sizes[0] / ROW_IN;

    const int smem_bytes = (WHF + 2 * XNF + 3 * BNF) * (int)sizeof(float);  // 212480

    int smcount = 0;
    cudaDeviceGetAttribute(&smcount, cudaDevAttrMultiProcessorCount, 0);
    if (smcount <= 0) smcount = 148;
    cudaFuncSetAttribute(tp_o3_mma_kernel, cudaFuncAttributeMaxDynamicSharedMemorySize,
                         smem_bytes);

    tp_o3_mma_kernel<<<smcount, THREADS, smem_bytes>>>(x1, x2, w, out, N);
}

// round 14
// speedup vs baseline: 1.3475x; 1.0346x over previous
#include <cuda_runtime.h>
#include <cuda_fp16.h>
#include <cstdint>

// PureCartesianTensorProductO3Sparse — R14: R13 + double-wide slots (2 mma
// passes per buffer slot, fp16 stage-1 buffer). Barrier rounds per tile: 4
// (was 8). Slots: (W0,W1), (W2,W3), (W4,W5V0), (W5V1,W5V2).

constexpr int ROW_IN  = 416;
constexpr int TILE    = 32;
constexpr int THREADS = 512;               // 8 producer + 8 consumer warps
constexpr int PTHREADS = 256;
constexpr int XSTR    = 212;
constexpr int HSTR    = 520;               // buffer row stride in halves (512+8)
constexpr int WELEMS  = 24576;
constexpr int WHF     = WELEMS / 2;        // weight halves in float-equivalents
constexpr int XNF     = TILE * XSTR;       // 6784
constexpr int BNH     = TILE * HSTR;       // 16640 halves per slot
// smem = 49152 + 54272 + 3*33280 = 203264 B

#define BAR_ARRIVE(id) asm volatile("bar.arrive %0, %1;" :: "r"(id), "r"(THREADS) : "memory")
#define BAR_SYNC(id)   asm volatile("bar.sync %0, %1;"   :: "r"(id), "r"(THREADS) : "memory")
// barrier ids: full[slot] = 1 + slot, empty[slot] = 4 + slot  (slots 0..2)

__device__ __forceinline__ uint32_t tf32_of(float f) {
    uint32_t u;
    asm("cvt.rna.tf32.f32 %0, %1;" : "=r"(u) : "f"(f));
    return u;
}

__device__ __forceinline__ void mma_tf32(float& d0, float& d1, float& d2, float& d3,
                                         uint32_t a0, uint32_t a1, uint32_t a2, uint32_t a3,
                                         uint32_t b0, uint32_t b1) {
    asm volatile(
        "mma.sync.aligned.m16n8k8.row.col.f32.tf32.tf32.f32 "
        "{%0,%1,%2,%3}, {%4,%5,%6,%7}, {%8,%9}, {%0,%1,%2,%3};\n"
        : "+f"(d0), "+f"(d1), "+f"(d2), "+f"(d3)
        : "r"(a0), "r"(a1), "r"(a2), "r"(a3), "r"(b0), "r"(b1));
}

__global__ __launch_bounds__(THREADS, 1)
void tp_o3_mma_kernel(const float* __restrict__ x1,
                      const float* __restrict__ x2,
                      const float* __restrict__ wgt,
                      float* __restrict__ out,
                      int N)
{
    extern __shared__ float smem[];
    __half* wsH = reinterpret_cast<__half*>(smem);   // fp16 weight fragments
    float* x1s  = smem + WHF;
    float* x2s  = x1s + XNF;
    __half* bufH = reinterpret_cast<__half*>(x2s + XNF);
    __half* bufs[3] = { bufH, bufH + BNH, bufH + 2 * BNH };

    const int tid = threadIdx.x;

    // ---- weight fill: gmem [p][o][a][b] -> fp16 fragment layout ----
    for (int idx = tid; idx < WELEMS; idx += THREADS) {
        int p = idx >> 12, o = (idx >> 8) & 15, a = (idx >> 4) & 15, b = idx & 15;
        int slot, col, k;
        if (p < 3)       { slot = p; col = (o << 4) + b; k = a; }
        else if (p == 3) { slot = 3; col = (o << 4) + a; k = b; }
        else if (p == 5) { slot = 4; col = (o << 4) + a; k = b; }
        else             { slot = 5; col = (o << 4) + a; k = b; }
        int pos = ((k & 3) << 2) | ((k >> 3) << 1) | ((k >> 2) & 1);
        wsH[(((slot << 8) + col) << 4) + pos] = __float2half(wgt[idx]);
    }
    __syncthreads();

    const int lane = tid & 31;
    const int wid  = tid >> 5;
    const bool producer = (wid < 8);

    if (!producer) { BAR_ARRIVE(4); BAR_ARRIVE(5); BAR_ARRIVE(6); }

    const int ntiles = (N + TILE - 1) / TILE;

    if (producer) {
        // ---------------- PRODUCER: tf32 mma stage-1 ----------------
        const int g   = lane >> 2;
        const int tg  = lane & 3;
        const int rb  = wid >> 2;           // rowblock 0/1
        const int nt0 = (wid & 3) << 3;     // 8 n-tiles per warp

        auto load_af = [&](uint32_t (&af)[2][4], const float* base, int koff, int kmul) {
            const float* xr0 = base + (rb * 16 + g) * XSTR + koff;
            const float* xr1 = xr0 + 8 * XSTR;
            #pragma unroll
            for (int ks = 0; ks < 2; ks++) {
                int k0 = ks * 8 + tg, k1 = k0 + 4;
                af[ks][0] = tf32_of(xr0[kmul * k0]);
                af[ks][1] = tf32_of(xr1[kmul * k0]);
                af[ks][2] = tf32_of(xr0[kmul * k1]);
                af[ks][3] = tf32_of(xr1[kmul * k1]);
            }
        };

        // one 256-col pass into chunk ch (0/1) of a slot buffer
        auto mma_pass = [&](int wslot, const uint32_t (&af)[2][4], __half* buf, int ch) {
            #pragma unroll
            for (int j = 0; j < 8; j++) {
                int nt  = nt0 + j;
                int col = nt * 8 + g;
                const uint2* bp = reinterpret_cast<const uint2*>(wsH)
                                + (((wslot << 8) + col) << 2) + tg;
                uint2 hw = *bp;
                __half2 h0 = *reinterpret_cast<__half2*>(&hw.x);
                __half2 h1 = *reinterpret_cast<__half2*>(&hw.y);
                float2 f0 = __half22float2(h0);
                float2 f1 = __half22float2(h1);
                uint32_t b00 = __float_as_uint(f0.x), b01 = __float_as_uint(f0.y);
                uint32_t b10 = __float_as_uint(f1.x), b11 = __float_as_uint(f1.y);
                float d0 = 0.f, d1 = 0.f, d2 = 0.f, d3 = 0.f;
                mma_tf32(d0, d1, d2, d3, af[0][0], af[0][1], af[0][2], af[0][3], b00, b01);
                mma_tf32(d0, d1, d2, d3, af[1][0], af[1][1], af[1][2], af[1][3], b10, b11);
                int r0 = rb * 16 + g;
                int hc = ch * 256 + nt * 8 + 2 * tg;
                *reinterpret_cast<__half2*>(buf + r0 * HSTR + hc)
                    = __floats2half2_rn(d0, d1);
                *reinterpret_cast<__half2*>(buf + (r0 + 8) * HSTR + hc)
                    = __floats2half2_rn(d2, d3);
            }
        };

        for (int tile = blockIdx.x; tile < ntiles; tile += (int)gridDim.x) {
            const int row0  = tile * TILE;
            const int nrows = min(TILE, N - row0);

            __syncthreads();   // consumers done with previous x
            {
                const float4* g1 = reinterpret_cast<const float4*>(x1) + (size_t)row0 * 104;
                const float4* g2 = reinterpret_cast<const float4*>(x2) + (size_t)row0 * 104;
                float4* s1 = reinterpret_cast<float4*>(x1s);
                float4* s2 = reinterpret_cast<float4*>(x2s);
                for (int i = tid; i < nrows * 52; i += THREADS) {
                    int r = i / 52, c = i - r * 52;
                    s1[r * 53 + c] = g1[(size_t)r * 104 + c];
                    s2[r * 53 + c] = g2[(size_t)r * 104 + c];
                }
            }
            __syncthreads();   // staging complete

            uint32_t afA[2][4], afB[2][4], afV[2][4];
            load_af(afA, x1s, 0, 1);        // A0 (W0,W1,W2)
            load_af(afB, x2s, 0, 1);        // B0 (W3,W4)

            // round 0: slot 0 = (W0, W1)
            BAR_SYNC(4);
            mma_pass(0, afA, bufs[0], 0);
            mma_pass(1, afA, bufs[0], 1);
            BAR_ARRIVE(1);

            // round 1: slot 1 = (W2, W3)
            BAR_SYNC(5);
            mma_pass(2, afA, bufs[1], 0);
            mma_pass(3, afB, bufs[1], 1);
            BAR_ARRIVE(2);

            // round 2: slot 2 = (W4, W5·V0)
            load_af(afV, x2s, 16, 3);       // B1t[0]
            BAR_SYNC(6);
            mma_pass(4, afB, bufs[2], 0);
            mma_pass(5, afV, bufs[2], 1);
            BAR_ARRIVE(3);

            // round 3: slot 0 = (W5·V1, W5·V2)
            load_af(afV, x2s, 17, 3);       // B1t[1]
            BAR_SYNC(4);
            mma_pass(5, afV, bufs[0], 0);
            load_af(afV, x2s, 18, 3);       // B1t[2]
            mma_pass(5, afV, bufs[0], 1);
            BAR_ARRIVE(1);

            // zero the s=1 output half while consumers finish
            {
                float4 z = make_float4(0.f, 0.f, 0.f, 0.f);
                float4* og = reinterpret_cast<float4*>(out) + (size_t)row0 * 104;
                for (int i = tid; i < nrows * 52; i += PTHREADS) {
                    int r = i / 52, c = i - r * 52;
                    og[(size_t)r * 104 + 52 + c] = z;
                }
            }
        }
    } else {
        // ---------------- CONSUMER: fp32 stage-2, 2 o-channels/thread -------
        const int ctid = tid - PTHREADS;
        const int row  = ctid >> 3;         // 0..31
        const int os   = ctid & 7;
        const int o1 = os, o2 = os + 8;

        float t1[16], t2[16];

        auto load_tt = [&](const __half* buf, int ch) {
            const int base = row * HSTR + ch * 256;
            const uint4* p1 = reinterpret_cast<const uint4*>(buf + base + (o1 << 4));
            const uint4* p2 = reinterpret_cast<const uint4*>(buf + base + (o2 << 4));
            uint4 qa = p1[0], qb = p1[1];
            uint4 qc = p2[0], qd = p2[1];
            const __half2* h;
            h = reinterpret_cast<const __half2*>(&qa);
            #pragma unroll
            for (int i = 0; i < 4; i++) { float2 f = __half22float2(h[i]); t1[2*i] = f.x; t1[2*i+1] = f.y; }
            h = reinterpret_cast<const __half2*>(&qb);
            #pragma unroll
            for (int i = 0; i < 4; i++) { float2 f = __half22float2(h[i]); t1[8+2*i] = f.x; t1[9+2*i] = f.y; }
            h = reinterpret_cast<const __half2*>(&qc);
            #pragma unroll
            for (int i = 0; i < 4; i++) { float2 f = __half22float2(h[i]); t2[2*i] = f.x; t2[2*i+1] = f.y; }
            h = reinterpret_cast<const __half2*>(&qd);
            #pragma unroll
            for (int i = 0; i < 4; i++) { float2 f = __half22float2(h[i]); t2[8+2*i] = f.x; t2[9+2*i] = f.y; }
        };

        for (int tile = blockIdx.x; tile < ntiles; tile += (int)gridDim.x) {
            const int row0  = tile * TILE;
            const int nrows = min(TILE, N - row0);
            const bool valid = (row < nrows);

            __syncthreads();
            {
                const float4* g1 = reinterpret_cast<const float4*>(x1) + (size_t)row0 * 104;
                const float4* g2 = reinterpret_cast<const float4*>(x2) + (size_t)row0 * 104;
                float4* s1 = reinterpret_cast<float4*>(x1s);
                float4* s2 = reinterpret_cast<float4*>(x2s);
                for (int i = tid; i < nrows * 52; i += THREADS) {
                    int r = i / 52, c = i - r * 52;
                    s1[r * 53 + c] = g1[(size_t)r * 104 + c];
                    s2[r * 53 + c] = g2[(size_t)r * 104 + c];
                }
            }
            __syncthreads();

            const float* xa = x1s + row * XSTR;
            const float* xb = x2s + row * XSTR;

            float acc0_1 = 0.f, acc0_2 = 0.f;
            float acc1_1[3] = {0.f,0.f,0.f}, acc1_2[3] = {0.f,0.f,0.f};
            float acc2_1[9] = {0.f,0.f,0.f,0.f,0.f,0.f,0.f,0.f,0.f};
            float acc2_2[9] = {0.f,0.f,0.f,0.f,0.f,0.f,0.f,0.f,0.f};

            // ---- round 0: slot 0 = (T0, T1)
            BAR_SYNC(1);
            if (valid) {
                load_tt(bufs[0], 0);
                {
                    float u1a=0.f,u1b=0.f,u2a=0.f,u2b=0.f;
                    #pragma unroll
                    for (int b = 0; b < 16; b += 2) {
                        float e0 = xb[b], e1 = xb[b+1];
                        u1a = fmaf(t1[b],   e0, u1a);
                        u1b = fmaf(t1[b+1], e1, u1b);
                        u2a = fmaf(t2[b],   e0, u2a);
                        u2b = fmaf(t2[b+1], e1, u2b);
                    }
                    acc0_1 = u1a + u1b; acc0_2 = u2a + u2b;
                }
                load_tt(bufs[0], 1);
                #pragma unroll
                for (int b = 0; b < 16; b++) {
                    float e0 = xb[16 + 3*b + 0];
                    float e1 = xb[16 + 3*b + 1];
                    float e2 = xb[16 + 3*b + 2];
                    acc1_1[0] = fmaf(t1[b], e0, acc1_1[0]);
                    acc1_1[1] = fmaf(t1[b], e1, acc1_1[1]);
                    acc1_1[2] = fmaf(t1[b], e2, acc1_1[2]);
                    acc1_2[0] = fmaf(t2[b], e0, acc1_2[0]);
                    acc1_2[1] = fmaf(t2[b], e1, acc1_2[1]);
                    acc1_2[2] = fmaf(t2[b], e2, acc1_2[2]);
                }
            }
            BAR_ARRIVE(4);

            // ---- round 1: slot 1 = (T2, S3)
            BAR_SYNC(2);
            if (valid) {
                load_tt(bufs[1], 0);
                #pragma unroll
                for (int b = 0; b < 16; b++) {
                    float tb1 = t1[b], tb2 = t2[b];
                    #pragma unroll
                    for (int k = 0; k < 9; k++) {
                        float e = xb[64 + 9*b + k];
                        acc2_1[k] = fmaf(tb1, e, acc2_1[k]);
                        acc2_2[k] = fmaf(tb2, e, acc2_2[k]);
                    }
                }
                load_tt(bufs[1], 1);
                #pragma unroll
                for (int a = 0; a < 16; a++) {
                    float e0 = xa[16 + 3*a + 0];
                    float e1 = xa[16 + 3*a + 1];
                    float e2 = xa[16 + 3*a + 2];
                    acc1_1[0] = fmaf(t1[a], e0, acc1_1[0]);
                    acc1_1[1] = fmaf(t1[a], e1, acc1_1[1]);
                    acc1_1[2] = fmaf(t1[a], e2, acc1_1[2]);
                    acc1_2[0] = fmaf(t2[a], e0, acc1_2[0]);
                    acc1_2[1] = fmaf(t2[a], e1, acc1_2[1]);
                    acc1_2[2] = fmaf(t2[a], e2, acc1_2[2]);
                }
            }
            BAR_ARRIVE(5);

            // ---- round 2: slot 2 = (S5, V0)
            BAR_SYNC(3);
            if (valid) {
                load_tt(bufs[2], 0);
                #pragma unroll
                for (int a = 0; a < 16; a++) {
                    float s1v = t1[a], s2v = t2[a];
                    #pragma unroll
                    for (int k = 0; k < 9; k++) {
                        float e = xa[64 + 9*a + k];
                        acc2_1[k] = fmaf(s1v, e, acc2_1[k]);
                        acc2_2[k] = fmaf(s2v, e, acc2_2[k]);
                    }
                }
                load_tt(bufs[2], 1);
                #pragma unroll
                for (int a = 0; a < 16; a++) {
                    float v1 = t1[a], v2 = t2[a];
                    float e0 = xa[16 + 3*a + 0];
                    float e1 = xa[16 + 3*a + 1];
                    float e2 = xa[16 + 3*a + 2];
                    acc2_1[0] = fmaf(v1, e0, acc2_1[0]);
                    acc2_1[3] = fmaf(v1, e1, acc2_1[3]);
                    acc2_1[6] = fmaf(v1, e2, acc2_1[6]);
                    acc2_2[0] = fmaf(v2, e0, acc2_2[0]);
                    acc2_2[3] = fmaf(v2, e1, acc2_2[3]);
                    acc2_2[6] = fmaf(v2, e2, acc2_2[6]);
                }
            }
            BAR_ARRIVE(6);

            // ---- round 3: slot 0 = (V1, V2)
            BAR_SYNC(1);
            if (valid) {
                #pragma unroll
                for (int ch = 0; ch < 2; ch++) {
                    load_tt(bufs[0], ch);
                    const int jj = 1 + ch;
                    #pragma unroll
                    for (int a = 0; a < 16; a++) {
                        float v1 = t1[a], v2 = t2[a];
                        float e0 = xa[16 + 3*a + 0];
                        float e1 = xa[16 + 3*a + 1];
                        float e2 = xa[16 + 3*a + 2];
                        acc2_1[0 + jj] = fmaf(v1, e0, acc2_1[0 + jj]);
                        acc2_1[3 + jj] = fmaf(v1, e1, acc2_1[3 + jj]);
                        acc2_1[6 + jj] = fmaf(v1, e2, acc2_1[6 + jj]);
                        acc2_2[0 + jj] = fmaf(v2, e0, acc2_2[0 + jj]);
                        acc2_2[3 + jj] = fmaf(v2, e1, acc2_2[3 + jj]);
                        acc2_2[6 + jj] = fmaf(v2, e2, acc2_2[6 + jj]);
                    }
                }
            }
            BAR_ARRIVE(4);

            // ---- write outputs (first half) for both o's ----
            if (valid) {
                float* orow = out + (size_t)(row0 + row) * ROW_IN;
                orow[o1] = acc0_1;
                orow[o2] = acc0_2;
                #pragma unroll
                for (int i = 0; i < 3; i++) {
                    orow[16 + 3*o1 + i] = acc1_1[i];
                    orow[16 + 3*o2 + i] = acc1_2[i];
                }
                #pragma unroll
                for (int k = 0; k < 9; k++) {
                    orow[64 + 9*o1 + k] = acc2_1[k];
                    orow[64 + 9*o2 + k] = acc2_2[k];
                }
            }
        }
    }
}

extern "C" void kernel_launch(void* const* d_in, const int* in_sizes, int n_in,
                              void* d_out, int out_size)
{
    const float* x1 = (const float*)d_in[0];
    const float* x2 = (const float*)d_in[1];
    const float* w  = (const float*)d_in[2];
    float* out = (float*)d_out;
    const int N = in_sizes[0] / ROW_IN;

    const int smem_bytes = (WHF + 2 * XNF) * (int)sizeof(float)
                         + 3 * BNH * (int)sizeof(__half);   // 203264

    int smcount = 0;
    cudaDeviceGetAttribute(&smcount, cudaDevAttrMultiProcessorCount, 0);
    if (smcount <= 0) smcount = 148;
    cudaFuncSetAttribute(tp_o3_mma_kernel, cudaFuncAttributeMaxDynamicSharedMemorySize,
                         smem_bytes);

    tp_o3_mma_kernel<<<smcount, THREADS, smem_bytes>>>(x1, x2, w, out, N);
}